// round 1
// baseline (speedup 1.0000x reference)
#include <cuda_runtime.h>
#include <math.h>

#define B_   1024
#define T_   64
#define D_   512
#define HID_ 256
#define NH_  4
#define HD_  128
#define BT_  (B_*T_)

// ---------------- scratch (static device globals; no allocation) ----------------
__device__ float g_zt[B_*D_];          // current ODE state
__device__ float g_k[4][B_*D_];        // RK4 stage outputs k1..k4
__device__ float g_h1[B_*HID_];        // field hidden 1
__device__ float g_h2[B_*HID_];        // field hidden 2
__device__ float g_zstack[(size_t)BT_*D_];   // [B,T,D] trajectory
__device__ float g_zmean[B_*D_];       // mean over T
__device__ float g_qkv[(size_t)BT_*3*D_];    // qkv buffer; first BT*D floats reused as att_out
__device__ float g_ctx[(size_t)BT_*D_];      // attention context

// ---------------- helpers ----------------
__device__ __forceinline__ float gelu_f(float x) {
    return 0.5f * x * (1.0f + erff(x * 0.70710678118654752f));
}

// ---------------- scale kernel: z0 = z_init * clip(||z||/(var+1e-6),0.8,1.2) ----------------
__global__ void scale_kernel(const float* __restrict__ zinit) {
    int b = blockIdx.x;
    int tid = threadIdx.x;                 // 256 threads
    const float* z = zinit + (size_t)b * D_;
    float s = 0.f, ss = 0.f;
    for (int i = tid; i < D_; i += 256) { float v = z[i]; s += v; ss += v * v; }
    __shared__ float rs[8], rss[8];
    for (int o = 16; o; o >>= 1) {
        s  += __shfl_down_sync(0xffffffffu, s,  o);
        ss += __shfl_down_sync(0xffffffffu, ss, o);
    }
    if ((tid & 31) == 0) { rs[tid >> 5] = s; rss[tid >> 5] = ss; }
    __syncthreads();
    float sum = 0.f, sumsq = 0.f;
    #pragma unroll
    for (int w = 0; w < 8; w++) { sum += rs[w]; sumsq += rss[w]; }
    float zn   = sqrtf(sumsq);
    float mean = sum * (1.0f / D_);
    float var  = (sumsq - sum * mean) * (1.0f / (D_ - 1));   // unbiased
    float sc   = zn / (var + 1e-6f);
    sc = fminf(fmaxf(sc, 0.8f), 1.2f);
    for (int i = tid; i < D_; i += 256) g_zt[(size_t)b * D_ + i] = z[i] * sc;
}

// ---------------- GEMM: C[M,N] = act( A @ B^T + bias ), A [M,K] row-major, B [N,K] row-major
// MODE 0: A = A1
// MODE 1: A = A1 + cmul*dt*A2   (dt from tsteps)
// MODE 2: A = z_dc:  A1=z_stack flat, A2=z_mean [B,D], A3=z_init [B,D]; b=row/T
// Tiles: 64x64x16, 128 threads, 8x4 micro-tile
#define BM 64
#define BN 64
#define BK 16

template<int MODE, bool GELU>
__global__ void gemm_nt(const float* __restrict__ A1, const float* __restrict__ A2,
                        const float* __restrict__ A3, float cmul,
                        const float* __restrict__ tsteps,
                        const float* __restrict__ Bw, const float* __restrict__ bias,
                        float* __restrict__ C, int M, int N, int K)
{
    __shared__ float As[BK][BM];
    __shared__ float Bs[BK][BN];
    int tid = threadIdx.x;                 // 128 threads
    int m0 = blockIdx.y * BM, n0 = blockIdx.x * BN;

    float c = 0.f;
    if (MODE == 1) c = cmul * (tsteps[1] - tsteps[0]);

    int lr = tid >> 2;                     // 0..31
    int lk = (tid & 3) * 4;                // 0,4,8,12

    int ty = tid >> 4;                     // 0..7  -> rows ty*8
    int tx = tid & 15;                     // 0..15 -> cols tx*4

    float acc[8][4];
    #pragma unroll
    for (int i = 0; i < 8; i++)
        #pragma unroll
        for (int j = 0; j < 4; j++) acc[i][j] = 0.f;

    for (int k0 = 0; k0 < K; k0 += BK) {
        #pragma unroll
        for (int rr = 0; rr < 2; rr++) {
            int r = lr + rr * 32;
            // ---- A tile ----
            int m = m0 + r;
            float4 a;
            if (MODE == 0) {
                a = *(const float4*)(A1 + (size_t)m * K + k0 + lk);
            } else if (MODE == 1) {
                float4 x = *(const float4*)(A1 + (size_t)m * K + k0 + lk);
                float4 y = *(const float4*)(A2 + (size_t)m * K + k0 + lk);
                a.x = x.x + c * y.x; a.y = x.y + c * y.y;
                a.z = x.z + c * y.z; a.w = x.w + c * y.w;
            } else {
                int b = m >> 6;  // /T_
                float4 zs = *(const float4*)(A1 + (size_t)m * K + k0 + lk);
                float4 zm = *(const float4*)(A2 + (size_t)b * D_ + k0 + lk);
                float4 zi = *(const float4*)(A3 + (size_t)b * D_ + k0 + lk);
                a.x = zs.x - 0.05f * (zm.x - zi.x);
                a.y = zs.y - 0.05f * (zm.y - zi.y);
                a.z = zs.z - 0.05f * (zm.z - zi.z);
                a.w = zs.w - 0.05f * (zm.w - zi.w);
            }
            As[lk + 0][r] = a.x; As[lk + 1][r] = a.y;
            As[lk + 2][r] = a.z; As[lk + 3][r] = a.w;
            // ---- B tile ----
            float4 bv = *(const float4*)(Bw + (size_t)(n0 + r) * K + k0 + lk);
            Bs[lk + 0][r] = bv.x; Bs[lk + 1][r] = bv.y;
            Bs[lk + 2][r] = bv.z; Bs[lk + 3][r] = bv.w;
        }
        __syncthreads();

        #pragma unroll
        for (int kk = 0; kk < BK; kk++) {
            float bfrag[4], afrag[8];
            *(float4*)&bfrag[0] = *(const float4*)&Bs[kk][tx * 4];
            *(float4*)&afrag[0] = *(const float4*)&As[kk][ty * 8];
            *(float4*)&afrag[4] = *(const float4*)&As[kk][ty * 8 + 4];
            #pragma unroll
            for (int i = 0; i < 8; i++)
                #pragma unroll
                for (int j = 0; j < 4; j++)
                    acc[i][j] += afrag[i] * bfrag[j];
        }
        __syncthreads();
    }

    float4 bsv = *(const float4*)(bias + n0 + tx * 4);
    float bb[4] = {bsv.x, bsv.y, bsv.z, bsv.w};
    #pragma unroll
    for (int i = 0; i < 8; i++) {
        int m = m0 + ty * 8 + i;
        float4 o;
        float v0 = acc[i][0] + bb[0];
        float v1 = acc[i][1] + bb[1];
        float v2 = acc[i][2] + bb[2];
        float v3 = acc[i][3] + bb[3];
        if (GELU) { v0 = gelu_f(v0); v1 = gelu_f(v1); v2 = gelu_f(v2); v3 = gelu_f(v3); }
        o.x = v0; o.y = v1; o.z = v2; o.w = v3;
        *(float4*)(C + (size_t)m * N + n0 + tx * 4) = o;
    }
}

// ---------------- RK4 combine: z_new = zt + dt/6*(k1+2k2+2k3+k4); nan->0 ----------------
__global__ void rk4_combine(const float* __restrict__ tsteps, int t) {
    int i = blockIdx.x * 256 + threadIdx.x;    // B*D
    float dt = tsteps[1] - tsteps[0];
    float z = g_zt[i] + dt * (1.0f / 6.0f) *
              (g_k[0][i] + 2.0f * g_k[1][i] + 2.0f * g_k[2][i] + g_k[3][i]);
    if (isnan(z)) z = 0.f;
    g_zt[i] = z;
    int b = i >> 9;       // /D_
    int d = i & 511;
    g_zstack[((size_t)(b * T_ + t)) * D_ + d] = z;
}

// ---------------- z_mean over T ----------------
__global__ void zmean_kernel() {
    int i = blockIdx.x * 256 + threadIdx.x;    // B*D
    int b = i >> 9, d = i & 511;
    const float* p = g_zstack + (size_t)b * T_ * D_ + d;
    float s = 0.f;
    #pragma unroll 8
    for (int t = 0; t < T_; t++) s += p[(size_t)t * D_];
    g_zmean[i] = s * (1.0f / T_);
}

// ---------------- fused per-(b,h) attention: softmax(QK^T/sqrt(HD)) V ----------------
#define QS_OFF 0                       // stride 129
#define KS_OFF (64*129)                // stride 129
#define VS_OFF (2*64*129)              // stride 128
#define S_OFF  (2*64*129 + 64*128)     // stride 65
#define ATTN_SMEM_BYTES ((2*64*129 + 64*128 + 64*65) * 4)

__global__ void attn_kernel() {
    extern __shared__ float sm[];
    float* Qs = sm + QS_OFF;
    float* Ks = sm + KS_OFF;
    float* Vs = sm + VS_OFF;
    float* S  = sm + S_OFF;
    __shared__ float red[64][4];

    int tid = threadIdx.x;             // 256
    int bh = blockIdx.x;
    int b = bh >> 2, h = bh & 3;

    // load Q,K,V [64,128]
    for (int idx = tid; idx < 64 * 128; idx += 256) {
        int t = idx >> 7, d = idx & 127;
        size_t base = ((size_t)(b * T_ + t)) * (3 * D_) + h * HD_ + d;
        Qs[t * 129 + d] = g_qkv[base];
        Ks[t * 129 + d] = g_qkv[base + D_];
        Vs[t * 128 + d] = g_qkv[base + 2 * D_];
    }
    __syncthreads();

    // scores: 4x4 micro-tile per thread
    {
        int ti = tid >> 4;             // i0 = ti*4
        int tj = tid & 15;             // j0 = tj*4
        float sacc[4][4];
        #pragma unroll
        for (int i = 0; i < 4; i++)
            #pragma unroll
            for (int j = 0; j < 4; j++) sacc[i][j] = 0.f;
        for (int kk = 0; kk < HD_; kk++) {
            float a[4], bq[4];
            #pragma unroll
            for (int i = 0; i < 4; i++) a[i]  = Qs[(ti * 4 + i) * 129 + kk];
            #pragma unroll
            for (int j = 0; j < 4; j++) bq[j] = Ks[(tj * 4 + j) * 129 + kk];
            #pragma unroll
            for (int i = 0; i < 4; i++)
                #pragma unroll
                for (int j = 0; j < 4; j++) sacc[i][j] += a[i] * bq[j];
        }
        const float sc = 0.08838834764831845f;   // 1/sqrt(128)
        #pragma unroll
        for (int i = 0; i < 4; i++)
            #pragma unroll
            for (int j = 0; j < 4; j++)
                S[(ti * 4 + i) * 65 + tj * 4 + j] = sacc[i][j] * sc;
    }
    __syncthreads();

    // softmax rows: 4 threads per row, 16 cols each
    {
        int r  = tid >> 2;
        int c4 = tid & 3;
        float* Srow = S + r * 65;
        float lmax = -1e30f;
        for (int j = c4 * 16; j < c4 * 16 + 16; j++) lmax = fmaxf(lmax, Srow[j]);
        red[r][c4] = lmax;
        __syncthreads();
        float m = fmaxf(fmaxf(red[r][0], red[r][1]), fmaxf(red[r][2], red[r][3]));
        __syncthreads();
        float lsum = 0.f;
        for (int j = c4 * 16; j < c4 * 16 + 16; j++) {
            float e = expf(Srow[j] - m);
            Srow[j] = e;
            lsum += e;
        }
        red[r][c4] = lsum;
        __syncthreads();
        float inv = 1.0f / (red[r][0] + red[r][1] + red[r][2] + red[r][3]);
        for (int j = c4 * 16; j < c4 * 16 + 16; j++) Srow[j] *= inv;
    }
    __syncthreads();

    // ctx = att @ V : 4 rows x 8 cols per thread
    {
        int ri = tid >> 4;             // i0 = ri*4
        int di = tid & 15;             // d0 = di*8
        float cacc[4][8];
        #pragma unroll
        for (int i = 0; i < 4; i++)
            #pragma unroll
            for (int j = 0; j < 8; j++) cacc[i][j] = 0.f;
        for (int j = 0; j < 64; j++) {
            float a[4];
            #pragma unroll
            for (int i = 0; i < 4; i++) a[i] = S[(ri * 4 + i) * 65 + j];
            float4 v0 = *(const float4*)&Vs[j * 128 + di * 8];
            float4 v1 = *(const float4*)&Vs[j * 128 + di * 8 + 4];
            #pragma unroll
            for (int i = 0; i < 4; i++) {
                cacc[i][0] += a[i] * v0.x; cacc[i][1] += a[i] * v0.y;
                cacc[i][2] += a[i] * v0.z; cacc[i][3] += a[i] * v0.w;
                cacc[i][4] += a[i] * v1.x; cacc[i][5] += a[i] * v1.y;
                cacc[i][6] += a[i] * v1.z; cacc[i][7] += a[i] * v1.w;
            }
        }
        #pragma unroll
        for (int i = 0; i < 4; i++) {
            int t = ri * 4 + i;
            size_t base = ((size_t)(b * T_ + t)) * D_ + h * HD_ + di * 8;
            float4 o0 = {cacc[i][0], cacc[i][1], cacc[i][2], cacc[i][3]};
            float4 o1 = {cacc[i][4], cacc[i][5], cacc[i][6], cacc[i][7]};
            *(float4*)&g_ctx[base]     = o0;
            *(float4*)&g_ctx[base + 4] = o1;
        }
    }
}

// ---------------- residual + LayerNorm epilogue ----------------
__global__ void ln_kernel(const float* __restrict__ zinit, const float* __restrict__ gamma,
                          const float* __restrict__ beta, float* __restrict__ out) {
    int row = blockIdx.x;              // b*T + t
    int b = row >> 6;
    int tid = threadIdx.x;             // 128
    const float* ao = g_qkv;           // att_out alias (first BT*D floats)
    float x[4];
    float s = 0.f, ss = 0.f;
    #pragma unroll
    for (int q = 0; q < 4; q++) {
        int d = tid + q * 128;
        float zs  = g_zstack[(size_t)row * D_ + d];
        float zdc = zs - 0.05f * (g_zmean[(size_t)b * D_ + d] - zinit[(size_t)b * D_ + d]);
        float v = zdc + ao[(size_t)row * D_ + d];
        x[q] = v; s += v; ss += v * v;
    }
    __shared__ float rs[4], rss[4];
    for (int o = 16; o; o >>= 1) {
        s  += __shfl_down_sync(0xffffffffu, s,  o);
        ss += __shfl_down_sync(0xffffffffu, ss, o);
    }
    if ((tid & 31) == 0) { rs[tid >> 5] = s; rss[tid >> 5] = ss; }
    __syncthreads();
    float sum   = rs[0] + rs[1] + rs[2] + rs[3];
    float sumsq = rss[0] + rss[1] + rss[2] + rss[3];
    float mean = sum * (1.0f / D_);
    float var  = sumsq * (1.0f / D_) - mean * mean;
    float inv  = rsqrtf(var + 1e-5f);
    #pragma unroll
    for (int q = 0; q < 4; q++) {
        int d = tid + q * 128;
        float o = (x[q] - mean) * inv * gamma[d] + beta[d];
        if (isnan(o)) o = 0.f;
        out[(size_t)row * D_ + d] = o;
    }
}

// ---------------- host orchestration ----------------
extern "C" void kernel_launch(void* const* d_in, const int* in_sizes, int n_in,
                              void* d_out, int out_size)
{
    const float* z_init = (const float*)d_in[0];
    const float* tsteps = (const float*)d_in[1];
    const float* W1     = (const float*)d_in[2];
    const float* b1     = (const float*)d_in[3];
    const float* W2     = (const float*)d_in[4];
    const float* b2     = (const float*)d_in[5];
    const float* W3     = (const float*)d_in[6];
    const float* b3     = (const float*)d_in[7];
    const float* Wqkv   = (const float*)d_in[8];
    const float* bqkv   = (const float*)d_in[9];
    const float* Wo     = (const float*)d_in[10];
    const float* bo     = (const float*)d_in[11];
    const float* gamma  = (const float*)d_in[12];
    const float* beta   = (const float*)d_in[13];

    float *zt, *kbase, *h1, *h2, *zstack, *zmean, *qkv, *ctx;
    cudaGetSymbolAddress((void**)&zt,     g_zt);
    cudaGetSymbolAddress((void**)&kbase,  g_k);
    cudaGetSymbolAddress((void**)&h1,     g_h1);
    cudaGetSymbolAddress((void**)&h2,     g_h2);
    cudaGetSymbolAddress((void**)&zstack, g_zstack);
    cudaGetSymbolAddress((void**)&zmean,  g_zmean);
    cudaGetSymbolAddress((void**)&qkv,    g_qkv);
    cudaGetSymbolAddress((void**)&ctx,    g_ctx);
    float* kp[4] = { kbase, kbase + (size_t)B_ * D_,
                     kbase + 2 * (size_t)B_ * D_, kbase + 3 * (size_t)B_ * D_ };

    cudaFuncSetAttribute(attn_kernel, cudaFuncAttributeMaxDynamicSharedMemorySize,
                         ATTN_SMEM_BYTES);

    // 1) input-adaptive scale
    scale_kernel<<<B_, 256>>>(z_init);

    // 2) RK4 trajectory
    const float cmuls[4] = {0.f, 0.5f, 0.5f, 1.f};
    dim3 g1(HID_ / BN, B_ / BM);   // layer1/layer2 grids (4,16)
    dim3 g3(D_ / BN,  B_ / BM);    // layer3 grid (8,16)
    for (int t = 0; t < T_; t++) {
        for (int e = 0; e < 4; e++) {
            if (e == 0)
                gemm_nt<0, true><<<g1, 128>>>(zt, nullptr, nullptr, 0.f, tsteps,
                                              W1, b1, h1, B_, HID_, D_);
            else
                gemm_nt<1, true><<<g1, 128>>>(zt, kp[e - 1], nullptr, cmuls[e], tsteps,
                                              W1, b1, h1, B_, HID_, D_);
            gemm_nt<0, true ><<<g1, 128>>>(h1, nullptr, nullptr, 0.f, tsteps,
                                           W2, b2, h2, B_, HID_, HID_);
            gemm_nt<0, false><<<g3, 128>>>(h2, nullptr, nullptr, 0.f, tsteps,
                                           W3, b3, kp[e], B_, D_, HID_);
        }
        rk4_combine<<<(B_ * D_) / 256, 256>>>(tsteps, t);
    }

    // 3) mean over T
    zmean_kernel<<<(B_ * D_) / 256, 256>>>();

    // 4) QKV projection with fused z_dc correction
    gemm_nt<2, false><<<dim3((3 * D_) / BN, BT_ / BM), 128>>>(
        zstack, zmean, z_init, 0.f, tsteps, Wqkv, bqkv, qkv, BT_, 3 * D_, D_);

    // 5) fused attention per (b,h)
    attn_kernel<<<B_ * NH_, 256, ATTN_SMEM_BYTES>>>();

    // 6) output projection (att_out aliased into qkv scratch)
    gemm_nt<0, false><<<dim3(D_ / BN, BT_ / BM), 128>>>(
        ctx, nullptr, nullptr, 0.f, tsteps, Wo, bo, qkv, BT_, D_, D_);

    // 7) residual + LayerNorm
    ln_kernel<<<BT_, 128>>>(z_init, gamma, beta, (float*)d_out);
}

// round 3
// speedup vs baseline: 3.3959x; 3.3959x over previous
#include <cuda_runtime.h>
#include <cuda_fp16.h>
#include <stdint.h>
#include <math.h>

#define B_   1024
#define T_   64
#define D_   512
#define HID_ 256
#define NH_  4
#define HD_  128
#define BT_  (B_*T_)

// ---------------- scratch ----------------
__device__ float g_zstack[(size_t)BT_*D_];   // [B,T,D] trajectory
__device__ float g_zmean[B_*D_];             // mean over T
__device__ float g_qkv[(size_t)BT_*3*D_];    // qkv buffer; first BT*D floats reused as att_out
__device__ float g_ctx[(size_t)BT_*D_];      // attention context
// packed fp16 fragment-major weights for the ODE field
__device__ __half g_W1p[HID_*D_];
__device__ __half g_W2p[HID_*HID_];
__device__ __half g_W3p[D_*HID_];

// ---------------- helpers ----------------
__device__ __forceinline__ float gelu_f(float x) {
    return 0.5f * x * (1.0f + erff(x * 0.70710678118654752f));
}

__device__ __forceinline__ void mma16816(float* c, uint32_t a0, uint32_t a1,
                                         uint32_t a2, uint32_t a3,
                                         uint32_t b0, uint32_t b1) {
    asm volatile(
        "mma.sync.aligned.m16n8k16.row.col.f32.f16.f16.f32 "
        "{%0,%1,%2,%3}, {%4,%5,%6,%7}, {%8,%9}, {%0,%1,%2,%3};\n"
        : "+f"(c[0]), "+f"(c[1]), "+f"(c[2]), "+f"(c[3])
        : "r"(a0), "r"(a1), "r"(a2), "r"(a3), "r"(b0), "r"(b1));
}

// ---------------- weight packing: fragment-major fp16 ----------------
// layout: out[((ks*nM + mt)*256) + lane*8 + j], j = [a0.lo,a0.hi,a1.lo,a1.hi,a2.lo,a2.hi,a3.lo,a3.hi]
__global__ void pack_w(const float* __restrict__ W, __half* __restrict__ out, int nM, int K) {
    int idx = blockIdx.x * 256 + threadIdx.x;
    int j    = idx & 7;
    int lane = (idx >> 3) & 31;
    int tile = idx >> 8;
    int mt = tile % nM;
    int ks = tile / nM;
    int gid = lane >> 2, tig = lane & 3;
    int rr = gid + ((j >> 1) & 1) * 8;
    int cc = tig * 2 + (j & 1) + ((j >> 2) & 1) * 8;
    int row = mt * 16 + rr;
    int col = ks * 16 + cc;
    out[idx] = __float2half_rn(W[(size_t)row * K + col]);
}

// ---------------- fused persistent ODE kernel ----------------
#define MB  16
#define ZP  516    // z pitch (floats)
#define ZBP 520    // zbf pitch (halfs)
#define HP  264    // h pitch (halfs)
#define SMEM_ODE (2*MB*ZP*4 + MB*ZBP*2 + 2*MB*HP*2)

template<int NM, int NK, bool GELU>
__device__ __forceinline__ void gemm_act(
    const __half* __restrict__ Wp, const float* __restrict__ bias,
    const __half* __restrict__ act, int ap,
    __half* __restrict__ out, int op, int warp, int lane)
{
    int gid = lane >> 2, tig = lane & 3;
    #pragma unroll
    for (int mt = warp; mt < NM; mt += 8) {
        float c0[4] = {0.f,0.f,0.f,0.f}, c1[4] = {0.f,0.f,0.f,0.f};
        const uint4* wp = (const uint4*)Wp + mt * 32 + lane;
        const __half* a0p = act + gid * ap + tig * 2;
        const __half* a1p = act + (gid + 8) * ap + tig * 2;
        #pragma unroll 8
        for (int ks = 0; ks < NK; ks++) {
            uint4 a = wp[(size_t)ks * NM * 32];
            uint32_t b00 = *(const uint32_t*)(a0p + ks * 16);
            uint32_t b01 = *(const uint32_t*)(a0p + ks * 16 + 8);
            uint32_t b10 = *(const uint32_t*)(a1p + ks * 16);
            uint32_t b11 = *(const uint32_t*)(a1p + ks * 16 + 8);
            mma16816(c0, a.x, a.y, a.z, a.w, b00, b01);
            mma16816(c1, a.x, a.y, a.z, a.w, b10, b11);
        }
        int h0 = mt * 16 + gid;
        float bs0 = __ldg(bias + h0);
        float bs1 = __ldg(bias + h0 + 8);
        int r = tig * 2;
        float v;
        v = c0[0] + bs0; if (GELU) v = gelu_f(v); out[(r + 0) * op + h0    ] = __float2half_rn(v);
        v = c0[1] + bs0; if (GELU) v = gelu_f(v); out[(r + 1) * op + h0    ] = __float2half_rn(v);
        v = c0[2] + bs1; if (GELU) v = gelu_f(v); out[(r + 0) * op + h0 + 8] = __float2half_rn(v);
        v = c0[3] + bs1; if (GELU) v = gelu_f(v); out[(r + 1) * op + h0 + 8] = __float2half_rn(v);
        v = c1[0] + bs0; if (GELU) v = gelu_f(v); out[(r + 8) * op + h0    ] = __float2half_rn(v);
        v = c1[1] + bs0; if (GELU) v = gelu_f(v); out[(r + 9) * op + h0    ] = __float2half_rn(v);
        v = c1[2] + bs1; if (GELU) v = gelu_f(v); out[(r + 8) * op + h0 + 8] = __float2half_rn(v);
        v = c1[3] + bs1; if (GELU) v = gelu_f(v); out[(r + 9) * op + h0 + 8] = __float2half_rn(v);
    }
}

__device__ __forceinline__ void gemm3_stage(
    const __half* __restrict__ Wp, const float* __restrict__ b3,
    const __half* __restrict__ act,
    float* Z, float* Zacc, __half* Zbf,
    float wcoef, float ccoef, bool doStage, int warp, int lane)
{
    constexpr int NM = 32, NK = 16;
    int gid = lane >> 2, tig = lane & 3;
    #pragma unroll
    for (int mt = warp; mt < NM; mt += 8) {
        float c0[4] = {0.f,0.f,0.f,0.f}, c1[4] = {0.f,0.f,0.f,0.f};
        const uint4* wp = (const uint4*)Wp + mt * 32 + lane;
        const __half* a0p = act + gid * HP + tig * 2;
        const __half* a1p = act + (gid + 8) * HP + tig * 2;
        #pragma unroll 8
        for (int ks = 0; ks < NK; ks++) {
            uint4 a = wp[(size_t)ks * NM * 32];
            uint32_t b00 = *(const uint32_t*)(a0p + ks * 16);
            uint32_t b01 = *(const uint32_t*)(a0p + ks * 16 + 8);
            uint32_t b10 = *(const uint32_t*)(a1p + ks * 16);
            uint32_t b11 = *(const uint32_t*)(a1p + ks * 16 + 8);
            mma16816(c0, a.x, a.y, a.z, a.w, b00, b01);
            mma16816(c1, a.x, a.y, a.z, a.w, b10, b11);
        }
        int d0 = mt * 16 + gid;
        float bv0 = __ldg(b3 + d0);
        float bv1 = __ldg(b3 + d0 + 8);
        int r = tig * 2;
        float k;
        #define ODE_DO(cc_, dd_, rr_, bb_)                                          \
            { k = (cc_) + (bb_);                                                    \
              Zacc[(rr_) * ZP + (dd_)] += wcoef * k;                                \
              if (doStage) Zbf[(rr_) * ZBP + (dd_)] =                               \
                  __float2half_rn(Z[(rr_) * ZP + (dd_)] + ccoef * k); }
        ODE_DO(c0[0], d0,     r,     bv0)
        ODE_DO(c0[1], d0,     r + 1, bv0)
        ODE_DO(c0[2], d0 + 8, r,     bv1)
        ODE_DO(c0[3], d0 + 8, r + 1, bv1)
        ODE_DO(c1[0], d0,     r + 8, bv0)
        ODE_DO(c1[1], d0,     r + 9, bv0)
        ODE_DO(c1[2], d0 + 8, r + 8, bv1)
        ODE_DO(c1[3], d0 + 8, r + 9, bv1)
        #undef ODE_DO
    }
}

__global__ void __launch_bounds__(256, 1) ode_kernel(
    const float* __restrict__ zinit, const float* __restrict__ tsteps,
    const float* __restrict__ b1, const float* __restrict__ b2,
    const float* __restrict__ b3)
{
    extern __shared__ char smchar[];
    float*  Z    = (float*)(smchar);
    float*  Zacc = (float*)(smchar + MB * ZP * 4);
    __half* Zbf  = (__half*)(smchar + 2 * MB * ZP * 4);
    __half* H1   = (__half*)(smchar + 2 * MB * ZP * 4 + MB * ZBP * 2);
    __half* H2   = H1 + MB * HP;

    int tid = threadIdx.x, warp = tid >> 5, lane = tid & 31;
    int r0 = blockIdx.x * MB;
    float dt = __ldg(tsteps + 1) - __ldg(tsteps);

    // ---- input-adaptive scale (16 threads per row) ----
    {
        int r = tid >> 4;
        int sub = tid & 15;
        const float* zr = zinit + (size_t)(r0 + r) * D_;
        float vals[32];
        float s = 0.f, ss = 0.f;
        #pragma unroll
        for (int i = 0; i < 32; i++) {
            float v = zr[sub + i * 16];
            vals[i] = v; s += v; ss += v * v;
        }
        for (int o = 8; o; o >>= 1) {
            s  += __shfl_down_sync(0xffffffffu, s,  o, 16);
            ss += __shfl_down_sync(0xffffffffu, ss, o, 16);
        }
        s  = __shfl_sync(0xffffffffu, s,  0, 16);
        ss = __shfl_sync(0xffffffffu, ss, 0, 16);
        float mean = s * (1.f / D_);
        float var  = (ss - s * mean) * (1.f / (D_ - 1));
        float sc   = sqrtf(ss) / (var + 1e-6f);
        sc = fminf(fmaxf(sc, 0.8f), 1.2f);
        #pragma unroll
        for (int i = 0; i < 32; i++) {
            float z = vals[i] * sc;
            int d = sub + i * 16;
            Z[r * ZP + d] = z;
            Zacc[r * ZP + d] = z;
            Zbf[r * ZBP + d] = __float2half_rn(z);
        }
    }
    __syncthreads();

    const float wc[4] = {1.f, 2.f, 2.f, 1.f};
    const float cc[4] = {0.5f, 0.5f, 1.f, 0.f};

    for (int t = 0; t < T_; t++) {
        #pragma unroll 1
        for (int e = 0; e < 4; e++) {
            gemm_act<16, 32, true>(g_W1p, b1, Zbf, ZBP, H1, HP, warp, lane);
            __syncthreads();
            gemm_act<16, 16, true>(g_W2p, b2, H1, HP, H2, HP, warp, lane);
            __syncthreads();
            gemm3_stage(g_W3p, b3, H2, Z, Zacc, Zbf,
                        dt * (1.f / 6.f) * wc[e], dt * cc[e], e < 3, warp, lane);
            __syncthreads();
        }
        // finalize step: z = zacc (nan->0), refresh buffers, emit trajectory
        #pragma unroll
        for (int j = 0; j < 32; j++) {
            int i = tid + j * 256;
            int r = i >> 9, d = i & 511;
            float z = Zacc[r * ZP + d];
            if (isnan(z)) z = 0.f;
            Z[r * ZP + d] = z;
            Zacc[r * ZP + d] = z;
            Zbf[r * ZBP + d] = __float2half_rn(z);
            g_zstack[((size_t)(r0 + r) * T_ + t) * D_ + d] = z;
        }
        __syncthreads();
    }
}

// ---------------- fp32 GEMM for attention-side projections ----------------
#define BM 64
#define BN 64
#define BK 16

template<int MODE, bool GELU>
__global__ void gemm_nt(const float* __restrict__ A1, const float* __restrict__ A2,
                        const float* __restrict__ A3,
                        const float* __restrict__ Bw, const float* __restrict__ bias,
                        float* __restrict__ C, int M, int N, int K)
{
    __shared__ float As[BK][BM];
    __shared__ float Bs[BK][BN];
    int tid = threadIdx.x;
    int m0 = blockIdx.y * BM, n0 = blockIdx.x * BN;

    int lr = tid >> 2;
    int lk = (tid & 3) * 4;
    int ty = tid >> 4;
    int tx = tid & 15;

    float acc[8][4];
    #pragma unroll
    for (int i = 0; i < 8; i++)
        #pragma unroll
        for (int j = 0; j < 4; j++) acc[i][j] = 0.f;

    for (int k0 = 0; k0 < K; k0 += BK) {
        #pragma unroll
        for (int rr = 0; rr < 2; rr++) {
            int r = lr + rr * 32;
            int m = m0 + r;
            float4 a;
            if (MODE == 0) {
                a = *(const float4*)(A1 + (size_t)m * K + k0 + lk);
            } else {
                int b = m >> 6;
                float4 zs = *(const float4*)(A1 + (size_t)m * K + k0 + lk);
                float4 zm = *(const float4*)(A2 + (size_t)b * D_ + k0 + lk);
                float4 zi = *(const float4*)(A3 + (size_t)b * D_ + k0 + lk);
                a.x = zs.x - 0.05f * (zm.x - zi.x);
                a.y = zs.y - 0.05f * (zm.y - zi.y);
                a.z = zs.z - 0.05f * (zm.z - zi.z);
                a.w = zs.w - 0.05f * (zm.w - zi.w);
            }
            As[lk + 0][r] = a.x; As[lk + 1][r] = a.y;
            As[lk + 2][r] = a.z; As[lk + 3][r] = a.w;
            float4 bv = *(const float4*)(Bw + (size_t)(n0 + r) * K + k0 + lk);
            Bs[lk + 0][r] = bv.x; Bs[lk + 1][r] = bv.y;
            Bs[lk + 2][r] = bv.z; Bs[lk + 3][r] = bv.w;
        }
        __syncthreads();

        #pragma unroll
        for (int kk = 0; kk < BK; kk++) {
            float bfrag[4], afrag[8];
            *(float4*)&bfrag[0] = *(const float4*)&Bs[kk][tx * 4];
            *(float4*)&afrag[0] = *(const float4*)&As[kk][ty * 8];
            *(float4*)&afrag[4] = *(const float4*)&As[kk][ty * 8 + 4];
            #pragma unroll
            for (int i = 0; i < 8; i++)
                #pragma unroll
                for (int j = 0; j < 4; j++)
                    acc[i][j] += afrag[i] * bfrag[j];
        }
        __syncthreads();
    }

    float4 bsv = *(const float4*)(bias + n0 + tx * 4);
    float bb[4] = {bsv.x, bsv.y, bsv.z, bsv.w};
    #pragma unroll
    for (int i = 0; i < 8; i++) {
        int m = m0 + ty * 8 + i;
        float4 o;
        float v0 = acc[i][0] + bb[0];
        float v1 = acc[i][1] + bb[1];
        float v2 = acc[i][2] + bb[2];
        float v3 = acc[i][3] + bb[3];
        if (GELU) { v0 = gelu_f(v0); v1 = gelu_f(v1); v2 = gelu_f(v2); v3 = gelu_f(v3); }
        o.x = v0; o.y = v1; o.z = v2; o.w = v3;
        *(float4*)(C + (size_t)m * N + n0 + tx * 4) = o;
    }
}

// ---------------- z_mean over T ----------------
__global__ void zmean_kernel() {
    int i = blockIdx.x * 256 + threadIdx.x;
    int b = i >> 9, d = i & 511;
    const float* p = g_zstack + (size_t)b * T_ * D_ + d;
    float s = 0.f;
    #pragma unroll 8
    for (int t = 0; t < T_; t++) s += p[(size_t)t * D_];
    g_zmean[i] = s * (1.0f / T_);
}

// ---------------- fused per-(b,h) attention ----------------
#define QS_OFF 0
#define KS_OFF (64*129)
#define VS_OFF (2*64*129)
#define S_OFF  (2*64*129 + 64*128)
#define ATTN_SMEM_BYTES ((2*64*129 + 64*128 + 64*65) * 4)

__global__ void attn_kernel() {
    extern __shared__ float sm[];
    float* Qs = sm + QS_OFF;
    float* Ks = sm + KS_OFF;
    float* Vs = sm + VS_OFF;
    float* S  = sm + S_OFF;
    __shared__ float red[64][4];

    int tid = threadIdx.x;
    int bh = blockIdx.x;
    int b = bh >> 2, h = bh & 3;

    for (int idx = tid; idx < 64 * 128; idx += 256) {
        int t = idx >> 7, d = idx & 127;
        size_t base = ((size_t)(b * T_ + t)) * (3 * D_) + h * HD_ + d;
        Qs[t * 129 + d] = g_qkv[base];
        Ks[t * 129 + d] = g_qkv[base + D_];
        Vs[t * 128 + d] = g_qkv[base + 2 * D_];
    }
    __syncthreads();

    {
        int ti = tid >> 4;
        int tj = tid & 15;
        float sacc[4][4];
        #pragma unroll
        for (int i = 0; i < 4; i++)
            #pragma unroll
            for (int j = 0; j < 4; j++) sacc[i][j] = 0.f;
        for (int kk = 0; kk < HD_; kk++) {
            float a[4], bq[4];
            #pragma unroll
            for (int i = 0; i < 4; i++) a[i]  = Qs[(ti * 4 + i) * 129 + kk];
            #pragma unroll
            for (int j = 0; j < 4; j++) bq[j] = Ks[(tj * 4 + j) * 129 + kk];
            #pragma unroll
            for (int i = 0; i < 4; i++)
                #pragma unroll
                for (int j = 0; j < 4; j++) sacc[i][j] += a[i] * bq[j];
        }
        const float sc = 0.08838834764831845f;
        #pragma unroll
        for (int i = 0; i < 4; i++)
            #pragma unroll
            for (int j = 0; j < 4; j++)
                S[(ti * 4 + i) * 65 + tj * 4 + j] = sacc[i][j] * sc;
    }
    __syncthreads();

    {
        int r  = tid >> 2;
        int c4 = tid & 3;
        float* Srow = S + r * 65;
        float lmax = -1e30f;
        for (int j = c4 * 16; j < c4 * 16 + 16; j++) lmax = fmaxf(lmax, Srow[j]);
        red[r][c4] = lmax;
        __syncthreads();
        float m = fmaxf(fmaxf(red[r][0], red[r][1]), fmaxf(red[r][2], red[r][3]));
        __syncthreads();
        float lsum = 0.f;
        for (int j = c4 * 16; j < c4 * 16 + 16; j++) {
            float e = expf(Srow[j] - m);
            Srow[j] = e;
            lsum += e;
        }
        red[r][c4] = lsum;
        __syncthreads();
        float inv = 1.0f / (red[r][0] + red[r][1] + red[r][2] + red[r][3]);
        for (int j = c4 * 16; j < c4 * 16 + 16; j++) Srow[j] *= inv;
    }
    __syncthreads();

    {
        int ri = tid >> 4;
        int di = tid & 15;
        float cacc[4][8];
        #pragma unroll
        for (int i = 0; i < 4; i++)
            #pragma unroll
            for (int j = 0; j < 8; j++) cacc[i][j] = 0.f;
        for (int j = 0; j < 64; j++) {
            float a[4];
            #pragma unroll
            for (int i = 0; i < 4; i++) a[i] = S[(ri * 4 + i) * 65 + j];
            float4 v0 = *(const float4*)&Vs[j * 128 + di * 8];
            float4 v1 = *(const float4*)&Vs[j * 128 + di * 8 + 4];
            #pragma unroll
            for (int i = 0; i < 4; i++) {
                cacc[i][0] += a[i] * v0.x; cacc[i][1] += a[i] * v0.y;
                cacc[i][2] += a[i] * v0.z; cacc[i][3] += a[i] * v0.w;
                cacc[i][4] += a[i] * v1.x; cacc[i][5] += a[i] * v1.y;
                cacc[i][6] += a[i] * v1.z; cacc[i][7] += a[i] * v1.w;
            }
        }
        #pragma unroll
        for (int i = 0; i < 4; i++) {
            int t = ri * 4 + i;
            size_t base = ((size_t)(b * T_ + t)) * D_ + h * HD_ + di * 8;
            float4 o0 = {cacc[i][0], cacc[i][1], cacc[i][2], cacc[i][3]};
            float4 o1 = {cacc[i][4], cacc[i][5], cacc[i][6], cacc[i][7]};
            *(float4*)&g_ctx[base]     = o0;
            *(float4*)&g_ctx[base + 4] = o1;
        }
    }
}

// ---------------- residual + LayerNorm ----------------
__global__ void ln_kernel(const float* __restrict__ zinit, const float* __restrict__ gamma,
                          const float* __restrict__ beta, float* __restrict__ out) {
    int row = blockIdx.x;
    int b = row >> 6;
    int tid = threadIdx.x;
    const float* ao = g_qkv;
    float x[4];
    float s = 0.f, ss = 0.f;
    #pragma unroll
    for (int q = 0; q < 4; q++) {
        int d = tid + q * 128;
        float zs  = g_zstack[(size_t)row * D_ + d];
        float zdc = zs - 0.05f * (g_zmean[(size_t)b * D_ + d] - zinit[(size_t)b * D_ + d]);
        float v = zdc + ao[(size_t)row * D_ + d];
        x[q] = v; s += v; ss += v * v;
    }
    __shared__ float rs[4], rss[4];
    for (int o = 16; o; o >>= 1) {
        s  += __shfl_down_sync(0xffffffffu, s,  o);
        ss += __shfl_down_sync(0xffffffffu, ss, o);
    }
    if ((tid & 31) == 0) { rs[tid >> 5] = s; rss[tid >> 5] = ss; }
    __syncthreads();
    float sum   = rs[0] + rs[1] + rs[2] + rs[3];
    float sumsq = rss[0] + rss[1] + rss[2] + rss[3];
    float mean = sum * (1.0f / D_);
    float var  = sumsq * (1.0f / D_) - mean * mean;
    float inv  = rsqrtf(var + 1e-5f);
    #pragma unroll
    for (int q = 0; q < 4; q++) {
        int d = tid + q * 128;
        float o = (x[q] - mean) * inv * gamma[d] + beta[d];
        if (isnan(o)) o = 0.f;
        out[(size_t)row * D_ + d] = o;
    }
}

// ---------------- host orchestration ----------------
extern "C" void kernel_launch(void* const* d_in, const int* in_sizes, int n_in,
                              void* d_out, int out_size)
{
    const float* z_init = (const float*)d_in[0];
    const float* tsteps = (const float*)d_in[1];
    const float* W1     = (const float*)d_in[2];
    const float* b1     = (const float*)d_in[3];
    const float* W2     = (const float*)d_in[4];
    const float* b2     = (const float*)d_in[5];
    const float* W3     = (const float*)d_in[6];
    const float* b3     = (const float*)d_in[7];
    const float* Wqkv   = (const float*)d_in[8];
    const float* bqkv   = (const float*)d_in[9];
    const float* Wo     = (const float*)d_in[10];
    const float* bo     = (const float*)d_in[11];
    const float* gamma  = (const float*)d_in[12];
    const float* beta   = (const float*)d_in[13];

    float *zstack, *zmean, *qkv, *ctx;
    __half *w1p, *w2p, *w3p;
    cudaGetSymbolAddress((void**)&zstack, g_zstack);
    cudaGetSymbolAddress((void**)&zmean,  g_zmean);
    cudaGetSymbolAddress((void**)&qkv,    g_qkv);
    cudaGetSymbolAddress((void**)&ctx,    g_ctx);
    cudaGetSymbolAddress((void**)&w1p,    g_W1p);
    cudaGetSymbolAddress((void**)&w2p,    g_W2p);
    cudaGetSymbolAddress((void**)&w3p,    g_W3p);

    cudaFuncSetAttribute(attn_kernel, cudaFuncAttributeMaxDynamicSharedMemorySize,
                         ATTN_SMEM_BYTES);
    cudaFuncSetAttribute(ode_kernel, cudaFuncAttributeMaxDynamicSharedMemorySize,
                         SMEM_ODE);

    // 0) pack field weights to fragment-major fp16
    pack_w<<<(HID_ * D_) / 256, 256>>>(W1, w1p, HID_ / 16, D_);
    pack_w<<<(HID_ * HID_) / 256, 256>>>(W2, w2p, HID_ / 16, HID_);
    pack_w<<<(D_ * HID_) / 256, 256>>>(W3, w3p, D_ / 16, HID_);

    // 1+2) fused scale + full RK4 trajectory
    ode_kernel<<<B_ / MB, 256, SMEM_ODE>>>(z_init, tsteps, b1, b2, b3);

    // 3) mean over T
    zmean_kernel<<<(B_ * D_) / 256, 256>>>();

    // 4) QKV projection with fused z_dc correction
    gemm_nt<2, false><<<dim3((3 * D_) / BN, BT_ / BM), 128>>>(
        zstack, zmean, z_init, Wqkv, bqkv, qkv, BT_, 3 * D_, D_);

    // 5) fused attention per (b,h)
    attn_kernel<<<B_ * NH_, 256, ATTN_SMEM_BYTES>>>();

    // 6) output projection (att_out aliased into qkv scratch)
    gemm_nt<0, false><<<dim3(D_ / BN, BT_ / BM), 128>>>(
        ctx, nullptr, nullptr, Wo, bo, qkv, BT_, D_, D_);

    // 7) residual + LayerNorm
    ln_kernel<<<BT_, 128>>>(z_init, gamma, beta, (float*)d_out);
}

// round 4
// speedup vs baseline: 6.0748x; 1.7889x over previous
#include <cuda_runtime.h>
#include <cuda_fp16.h>
#include <stdint.h>
#include <math.h>

#define B_   1024
#define T_   64
#define D_   512
#define HID_ 256
#define NH_  4
#define HD_  128
#define BT_  (B_*T_)

// ---------------- scratch ----------------
__device__ float  g_zstack[(size_t)BT_*D_];   // [B,T,D] trajectory (fp32)
__device__ float  g_zmean[B_*D_];             // mean over T
__device__ float  g_qkv[(size_t)BT_*3*D_];    // qkv fp32; first BT*D reused as att_out
__device__ __half g_zdc[(size_t)BT_*D_];      // z_dc fp16 activations for QKV gemm
__device__ __half g_ctxh[(size_t)BT_*D_];     // attention context fp16
// packed fp16 fragment-major weights
__device__ __half g_W1p[HID_*D_];
__device__ __half g_W2p[HID_*HID_];
__device__ __half g_W3p[D_*HID_];
__device__ __half g_Wqkvf[3*D_*D_];
__device__ __half g_Wof[D_*D_];

// ---------------- helpers ----------------
__device__ __forceinline__ float gelu_f(float x) {
    return 0.5f * x * (1.0f + erff(x * 0.70710678118654752f));
}

__device__ __forceinline__ void mma16816(float* c, uint32_t a0, uint32_t a1,
                                         uint32_t a2, uint32_t a3,
                                         uint32_t b0, uint32_t b1) {
    asm volatile(
        "mma.sync.aligned.m16n8k16.row.col.f32.f16.f16.f32 "
        "{%0,%1,%2,%3}, {%4,%5,%6,%7}, {%8,%9}, {%0,%1,%2,%3};\n"
        : "+f"(c[0]), "+f"(c[1]), "+f"(c[2]), "+f"(c[3])
        : "r"(a0), "r"(a1), "r"(a2), "r"(a3), "r"(b0), "r"(b1));
}

__device__ __forceinline__ void ldsm_x4(uint32_t& a0, uint32_t& a1, uint32_t& a2,
                                        uint32_t& a3, uint32_t saddr) {
    asm volatile("ldmatrix.sync.aligned.m8n8.x4.shared.b16 {%0,%1,%2,%3}, [%4];\n"
                 : "=r"(a0), "=r"(a1), "=r"(a2), "=r"(a3) : "r"(saddr));
}

__device__ __forceinline__ uint32_t smem_u32(const void* p) {
    uint32_t a;
    asm("{ .reg .u64 t; cvta.to.shared.u64 t, %1; cvt.u32.u64 %0, t; }"
        : "=r"(a) : "l"(p));
    return a;
}

// ---------------- weight packing (A-operand fragment-major, for ODE) ----------------
__global__ void pack_w(const float* __restrict__ W, __half* __restrict__ out, int nM, int K) {
    int idx = blockIdx.x * 256 + threadIdx.x;
    int j    = idx & 7;
    int lane = (idx >> 3) & 31;
    int tile = idx >> 8;
    int mt = tile % nM;
    int ks = tile / nM;
    int gid = lane >> 2, tig = lane & 3;
    int rr = gid + ((j >> 1) & 1) * 8;
    int cc = tig * 2 + (j & 1) + ((j >> 2) & 1) * 8;
    out[idx] = __float2half_rn(W[(size_t)(mt * 16 + rr) * K + ks * 16 + cc]);
}

// ---------------- weight packing (B-operand fragment-major, for hgemm) ----------------
// half layout: out[(((nt*NKS+ks)*32+lane)*4) + h], h: {b0.lo,b0.hi,b1.lo,b1.hi}
__global__ void pack_wb(const float* __restrict__ W, __half* __restrict__ out, int N, int K) {
    int idx = blockIdx.x * 256 + threadIdx.x;
    if (idx >= N * K) return;
    int h    = idx & 3;
    int lane = (idx >> 2) & 31;
    int rest = idx >> 7;
    int NKS = K / 16;
    int ks = rest % NKS;
    int nt = rest / NKS;
    int n = nt * 8 + (lane >> 2);
    int k = ks * 16 + (lane & 3) * 2 + (h & 1) + ((h >> 1) << 3);
    out[idx] = __float2half_rn(W[(size_t)n * K + k]);
}

// ---------------- fused persistent ODE kernel (512 threads, 16 warps) ----------------
#define MB  16
#define ZP  516
#define ZBP 520
#define HP  264
#define SMEM_ODE (2*MB*ZP*4 + MB*ZBP*2 + 2*MB*HP*2)

template<int NM, int NK, bool GELU>
__device__ __forceinline__ void gemm_act(
    const __half* __restrict__ Wp, const float* __restrict__ bias,
    const __half* __restrict__ act, int ap,
    __half* __restrict__ out, int op, int warp, int lane)
{
    int gid = lane >> 2, tig = lane & 3;
    #pragma unroll
    for (int mt = warp; mt < NM; mt += 16) {
        float c0[4] = {0.f,0.f,0.f,0.f}, c1[4] = {0.f,0.f,0.f,0.f};
        const uint4* wp = (const uint4*)Wp + mt * 32 + lane;
        const __half* a0p = act + gid * ap + tig * 2;
        const __half* a1p = act + (gid + 8) * ap + tig * 2;
        #pragma unroll 8
        for (int ks = 0; ks < NK; ks++) {
            uint4 a = wp[(size_t)ks * NM * 32];
            uint32_t b00 = *(const uint32_t*)(a0p + ks * 16);
            uint32_t b01 = *(const uint32_t*)(a0p + ks * 16 + 8);
            uint32_t b10 = *(const uint32_t*)(a1p + ks * 16);
            uint32_t b11 = *(const uint32_t*)(a1p + ks * 16 + 8);
            mma16816(c0, a.x, a.y, a.z, a.w, b00, b01);
            mma16816(c1, a.x, a.y, a.z, a.w, b10, b11);
        }
        int h0 = mt * 16 + gid;
        float bs0 = __ldg(bias + h0);
        float bs1 = __ldg(bias + h0 + 8);
        int r = tig * 2;
        float v;
        v = c0[0] + bs0; if (GELU) v = gelu_f(v); out[(r + 0) * op + h0    ] = __float2half_rn(v);
        v = c0[1] + bs0; if (GELU) v = gelu_f(v); out[(r + 1) * op + h0    ] = __float2half_rn(v);
        v = c0[2] + bs1; if (GELU) v = gelu_f(v); out[(r + 0) * op + h0 + 8] = __float2half_rn(v);
        v = c0[3] + bs1; if (GELU) v = gelu_f(v); out[(r + 1) * op + h0 + 8] = __float2half_rn(v);
        v = c1[0] + bs0; if (GELU) v = gelu_f(v); out[(r + 8) * op + h0    ] = __float2half_rn(v);
        v = c1[1] + bs0; if (GELU) v = gelu_f(v); out[(r + 9) * op + h0    ] = __float2half_rn(v);
        v = c1[2] + bs1; if (GELU) v = gelu_f(v); out[(r + 8) * op + h0 + 8] = __float2half_rn(v);
        v = c1[3] + bs1; if (GELU) v = gelu_f(v); out[(r + 9) * op + h0 + 8] = __float2half_rn(v);
    }
}

__device__ __forceinline__ void gemm3_stage(
    const __half* __restrict__ Wp, const float* __restrict__ b3,
    const __half* __restrict__ act,
    float* Z, float* Zacc, __half* Zbf,
    float wcoef, float ccoef, bool doStage, int warp, int lane)
{
    constexpr int NM = 32, NK = 16;
    int gid = lane >> 2, tig = lane & 3;
    #pragma unroll
    for (int mt = warp; mt < NM; mt += 16) {
        float c0[4] = {0.f,0.f,0.f,0.f}, c1[4] = {0.f,0.f,0.f,0.f};
        const uint4* wp = (const uint4*)Wp + mt * 32 + lane;
        const __half* a0p = act + gid * HP + tig * 2;
        const __half* a1p = act + (gid + 8) * HP + tig * 2;
        #pragma unroll 8
        for (int ks = 0; ks < NK; ks++) {
            uint4 a = wp[(size_t)ks * NM * 32];
            uint32_t b00 = *(const uint32_t*)(a0p + ks * 16);
            uint32_t b01 = *(const uint32_t*)(a0p + ks * 16 + 8);
            uint32_t b10 = *(const uint32_t*)(a1p + ks * 16);
            uint32_t b11 = *(const uint32_t*)(a1p + ks * 16 + 8);
            mma16816(c0, a.x, a.y, a.z, a.w, b00, b01);
            mma16816(c1, a.x, a.y, a.z, a.w, b10, b11);
        }
        int d0 = mt * 16 + gid;
        float bv0 = __ldg(b3 + d0);
        float bv1 = __ldg(b3 + d0 + 8);
        int r = tig * 2;
        float k;
        #define ODE_DO(cc_, dd_, rr_, bb_)                                          \
            { k = (cc_) + (bb_);                                                    \
              Zacc[(rr_) * ZP + (dd_)] += wcoef * k;                                \
              if (doStage) Zbf[(rr_) * ZBP + (dd_)] =                               \
                  __float2half_rn(Z[(rr_) * ZP + (dd_)] + ccoef * k); }
        ODE_DO(c0[0], d0,     r,     bv0)
        ODE_DO(c0[1], d0,     r + 1, bv0)
        ODE_DO(c0[2], d0 + 8, r,     bv1)
        ODE_DO(c0[3], d0 + 8, r + 1, bv1)
        ODE_DO(c1[0], d0,     r + 8, bv0)
        ODE_DO(c1[1], d0,     r + 9, bv0)
        ODE_DO(c1[2], d0 + 8, r + 8, bv1)
        ODE_DO(c1[3], d0 + 8, r + 9, bv1)
        #undef ODE_DO
    }
}

__global__ void __launch_bounds__(512, 1) ode_kernel(
    const float* __restrict__ zinit, const float* __restrict__ tsteps,
    const float* __restrict__ b1, const float* __restrict__ b2,
    const float* __restrict__ b3)
{
    extern __shared__ char smchar[];
    float*  Z    = (float*)(smchar);
    float*  Zacc = (float*)(smchar + MB * ZP * 4);
    __half* Zbf  = (__half*)(smchar + 2 * MB * ZP * 4);
    __half* H1   = (__half*)(smchar + 2 * MB * ZP * 4 + MB * ZBP * 2);
    __half* H2   = H1 + MB * HP;

    int tid = threadIdx.x, warp = tid >> 5, lane = tid & 31;
    int r0 = blockIdx.x * MB;
    float dt = __ldg(tsteps + 1) - __ldg(tsteps);

    // ---- input-adaptive scale (one warp per row) ----
    {
        int r = warp;                  // 0..15
        int sub = lane;
        const float* zr = zinit + (size_t)(r0 + r) * D_;
        float vals[16];
        float s = 0.f, ss = 0.f;
        #pragma unroll
        for (int i = 0; i < 16; i++) {
            float v = zr[sub + i * 32];
            vals[i] = v; s += v; ss += v * v;
        }
        for (int o = 16; o; o >>= 1) {
            s  += __shfl_down_sync(0xffffffffu, s,  o);
            ss += __shfl_down_sync(0xffffffffu, ss, o);
        }
        s  = __shfl_sync(0xffffffffu, s,  0);
        ss = __shfl_sync(0xffffffffu, ss, 0);
        float mean = s * (1.f / D_);
        float var  = (ss - s * mean) * (1.f / (D_ - 1));
        float sc   = sqrtf(ss) / (var + 1e-6f);
        sc = fminf(fmaxf(sc, 0.8f), 1.2f);
        #pragma unroll
        for (int i = 0; i < 16; i++) {
            float z = vals[i] * sc;
            int d = sub + i * 32;
            Z[r * ZP + d] = z;
            Zacc[r * ZP + d] = z;
            Zbf[r * ZBP + d] = __float2half_rn(z);
        }
    }
    __syncthreads();

    const float wc[4] = {1.f, 2.f, 2.f, 1.f};
    const float cc[4] = {0.5f, 0.5f, 1.f, 0.f};

    for (int t = 0; t < T_; t++) {
        #pragma unroll 1
        for (int e = 0; e < 4; e++) {
            gemm_act<16, 32, true>(g_W1p, b1, Zbf, ZBP, H1, HP, warp, lane);
            __syncthreads();
            gemm_act<16, 16, true>(g_W2p, b2, H1, HP, H2, HP, warp, lane);
            __syncthreads();
            gemm3_stage(g_W3p, b3, H2, Z, Zacc, Zbf,
                        dt * (1.f / 6.f) * wc[e], dt * cc[e], e < 3, warp, lane);
            __syncthreads();
        }
        #pragma unroll
        for (int j = 0; j < 16; j++) {
            int i = tid + j * 512;
            int r = i >> 9, d = i & 511;
            float z = Zacc[r * ZP + d];
            if (isnan(z)) z = 0.f;
            Z[r * ZP + d] = z;
            Zacc[r * ZP + d] = z;
            Zbf[r * ZBP + d] = __float2half_rn(z);
            g_zstack[((size_t)(r0 + r) * T_ + t) * D_ + d] = z;
        }
        __syncthreads();
    }
}

// ---------------- hgemm: C[M,N] fp32 = Act[M,512] fp16 @ Wfrag^T + bias ----------------
// CTA: 256 threads (8 warps), 128 rows, sweeps all N. K=512.
#define AP 520
#define SMEM_HG (128*AP*2)

template<int NTOT>
__global__ void __launch_bounds__(256, 1) hgemm(
    const __half* __restrict__ Act, const __half* __restrict__ Wf,
    const float* __restrict__ bias, float* __restrict__ C)
{
    extern __shared__ __half As[];
    int tid = threadIdx.x, warp = tid >> 5, lane = tid & 31;
    int m0 = blockIdx.x * 128;

    for (int i = tid; i < 128 * 64; i += 256) {
        int r = i >> 6, c = i & 63;
        *(uint4*)&As[r * AP + c * 8] = *(const uint4*)&Act[(size_t)(m0 + r) * 512 + c * 8];
    }
    __syncthreads();

    int mw = warp * 16;
    int arow = mw + (lane & 7) + ((lane >> 3) & 1) * 8;
    int acol = ((lane >> 4) & 1) * 8;
    uint32_t abase = smem_u32(As) + (arow * AP + acol) * 2;

    int r = lane >> 2, cpair = (lane & 3) * 2;

    for (int ng = 0; ng < NTOT / 64; ng++) {
        float acc[8][4];
        #pragma unroll
        for (int j = 0; j < 8; j++)
            #pragma unroll
            for (int q = 0; q < 4; q++) acc[j][q] = 0.f;

        const uint2* wbase = (const uint2*)Wf + ((size_t)ng * 8 * 32) * 32 + lane;
        #pragma unroll 4
        for (int ks = 0; ks < 32; ks++) {
            uint32_t a0, a1, a2, a3;
            ldsm_x4(a0, a1, a2, a3, abase + ks * 32);
            #pragma unroll
            for (int j = 0; j < 8; j++) {
                uint2 b = wbase[((size_t)j * 32 + ks) * 32];
                mma16816(acc[j], a0, a1, a2, a3, b.x, b.y);
            }
        }
        #pragma unroll
        for (int j = 0; j < 8; j++) {
            int n = ng * 64 + j * 8 + cpair;
            float bv0 = __ldg(bias + n), bv1 = __ldg(bias + n + 1);
            float2 lo = make_float2(acc[j][0] + bv0, acc[j][1] + bv1);
            float2 hi = make_float2(acc[j][2] + bv0, acc[j][3] + bv1);
            *(float2*)&C[(size_t)(m0 + mw + r)     * NTOT + n] = lo;
            *(float2*)&C[(size_t)(m0 + mw + r + 8) * NTOT + n] = hi;
        }
    }
}

// ---------------- z_mean over T ----------------
__global__ void zmean_kernel() {
    int i = blockIdx.x * 256 + threadIdx.x;
    int b = i >> 9, d = i & 511;
    const float* p = g_zstack + (size_t)b * T_ * D_ + d;
    float s = 0.f;
    #pragma unroll 8
    for (int t = 0; t < T_; t++) s += p[(size_t)t * D_];
    g_zmean[i] = s * (1.0f / T_);
}

// ---------------- z_dc fp16 prep ----------------
__global__ void zdc_kernel(const float* __restrict__ zinit) {
    size_t i = (size_t)blockIdx.x * 256 + threadIdx.x;
    int row = (int)(i >> 9);
    int d = (int)(i & 511);
    int b = row >> 6;
    float v = g_zstack[i] - 0.05f * (g_zmean[b * D_ + d] - zinit[(size_t)b * D_ + d]);
    g_zdc[i] = __float2half_rn(v);
}

// ---------------- fused per-(b,h) attention (fp32 math, fp16 ctx out) ----------------
#define QS_OFF 0
#define KS_OFF (64*129)
#define VS_OFF (2*64*129)
#define S_OFF  (2*64*129 + 64*128)
#define ATTN_SMEM_BYTES ((2*64*129 + 64*128 + 64*65) * 4)

__global__ void attn_kernel() {
    extern __shared__ float sm[];
    float* Qs = sm + QS_OFF;
    float* Ks = sm + KS_OFF;
    float* Vs = sm + VS_OFF;
    float* S  = sm + S_OFF;
    __shared__ float red[64][4];

    int tid = threadIdx.x;
    int bh = blockIdx.x;
    int b = bh >> 2, h = bh & 3;

    for (int idx = tid; idx < 64 * 128; idx += 256) {
        int t = idx >> 7, d = idx & 127;
        size_t base = ((size_t)(b * T_ + t)) * (3 * D_) + h * HD_ + d;
        Qs[t * 129 + d] = g_qkv[base];
        Ks[t * 129 + d] = g_qkv[base + D_];
        Vs[t * 128 + d] = g_qkv[base + 2 * D_];
    }
    __syncthreads();

    {
        int ti = tid >> 4;
        int tj = tid & 15;
        float sacc[4][4];
        #pragma unroll
        for (int i = 0; i < 4; i++)
            #pragma unroll
            for (int j = 0; j < 4; j++) sacc[i][j] = 0.f;
        for (int kk = 0; kk < HD_; kk++) {
            float a[4], bq[4];
            #pragma unroll
            for (int i = 0; i < 4; i++) a[i]  = Qs[(ti * 4 + i) * 129 + kk];
            #pragma unroll
            for (int j = 0; j < 4; j++) bq[j] = Ks[(tj * 4 + j) * 129 + kk];
            #pragma unroll
            for (int i = 0; i < 4; i++)
                #pragma unroll
                for (int j = 0; j < 4; j++) sacc[i][j] += a[i] * bq[j];
        }
        const float sc = 0.08838834764831845f;
        #pragma unroll
        for (int i = 0; i < 4; i++)
            #pragma unroll
            for (int j = 0; j < 4; j++)
                S[(ti * 4 + i) * 65 + tj * 4 + j] = sacc[i][j] * sc;
    }
    __syncthreads();

    {
        int r  = tid >> 2;
        int c4 = tid & 3;
        float* Srow = S + r * 65;
        float lmax = -1e30f;
        for (int j = c4 * 16; j < c4 * 16 + 16; j++) lmax = fmaxf(lmax, Srow[j]);
        red[r][c4] = lmax;
        __syncthreads();
        float m = fmaxf(fmaxf(red[r][0], red[r][1]), fmaxf(red[r][2], red[r][3]));
        __syncthreads();
        float lsum = 0.f;
        for (int j = c4 * 16; j < c4 * 16 + 16; j++) {
            float e = expf(Srow[j] - m);
            Srow[j] = e;
            lsum += e;
        }
        red[r][c4] = lsum;
        __syncthreads();
        float inv = 1.0f / (red[r][0] + red[r][1] + red[r][2] + red[r][3]);
        for (int j = c4 * 16; j < c4 * 16 + 16; j++) Srow[j] *= inv;
    }
    __syncthreads();

    {
        int ri = tid >> 4;
        int di = tid & 15;
        float cacc[4][8];
        #pragma unroll
        for (int i = 0; i < 4; i++)
            #pragma unroll
            for (int j = 0; j < 8; j++) cacc[i][j] = 0.f;
        for (int j = 0; j < 64; j++) {
            float a[4];
            #pragma unroll
            for (int i = 0; i < 4; i++) a[i] = S[(ri * 4 + i) * 65 + j];
            float4 v0 = *(const float4*)&Vs[j * 128 + di * 8];
            float4 v1 = *(const float4*)&Vs[j * 128 + di * 8 + 4];
            #pragma unroll
            for (int i = 0; i < 4; i++) {
                cacc[i][0] += a[i] * v0.x; cacc[i][1] += a[i] * v0.y;
                cacc[i][2] += a[i] * v0.z; cacc[i][3] += a[i] * v0.w;
                cacc[i][4] += a[i] * v1.x; cacc[i][5] += a[i] * v1.y;
                cacc[i][6] += a[i] * v1.z; cacc[i][7] += a[i] * v1.w;
            }
        }
        #pragma unroll
        for (int i = 0; i < 4; i++) {
            int t = ri * 4 + i;
            size_t base = ((size_t)(b * T_ + t)) * D_ + h * HD_ + di * 8;
            __half2 p0 = __floats2half2_rn(cacc[i][0], cacc[i][1]);
            __half2 p1 = __floats2half2_rn(cacc[i][2], cacc[i][3]);
            __half2 p2 = __floats2half2_rn(cacc[i][4], cacc[i][5]);
            __half2 p3 = __floats2half2_rn(cacc[i][6], cacc[i][7]);
            uint4 u;
            u.x = *(uint32_t*)&p0; u.y = *(uint32_t*)&p1;
            u.z = *(uint32_t*)&p2; u.w = *(uint32_t*)&p3;
            *(uint4*)&g_ctxh[base] = u;
        }
    }
}

// ---------------- residual + LayerNorm ----------------
__global__ void ln_kernel(const float* __restrict__ zinit, const float* __restrict__ gamma,
                          const float* __restrict__ beta, float* __restrict__ out) {
    int row = blockIdx.x;
    int b = row >> 6;
    int tid = threadIdx.x;
    const float* ao = g_qkv;
    float x[4];
    float s = 0.f, ss = 0.f;
    #pragma unroll
    for (int q = 0; q < 4; q++) {
        int d = tid + q * 128;
        float zs  = g_zstack[(size_t)row * D_ + d];
        float zdc = zs - 0.05f * (g_zmean[(size_t)b * D_ + d] - zinit[(size_t)b * D_ + d]);
        float v = zdc + ao[(size_t)row * D_ + d];
        x[q] = v; s += v; ss += v * v;
    }
    __shared__ float rs[4], rss[4];
    for (int o = 16; o; o >>= 1) {
        s  += __shfl_down_sync(0xffffffffu, s,  o);
        ss += __shfl_down_sync(0xffffffffu, ss, o);
    }
    if ((tid & 31) == 0) { rs[tid >> 5] = s; rss[tid >> 5] = ss; }
    __syncthreads();
    float sum   = rs[0] + rs[1] + rs[2] + rs[3];
    float sumsq = rss[0] + rss[1] + rss[2] + rss[3];
    float mean = sum * (1.0f / D_);
    float var  = sumsq * (1.0f / D_) - mean * mean;
    float inv  = rsqrtf(var + 1e-5f);
    #pragma unroll
    for (int q = 0; q < 4; q++) {
        int d = tid + q * 128;
        float o = (x[q] - mean) * inv * gamma[d] + beta[d];
        if (isnan(o)) o = 0.f;
        out[(size_t)row * D_ + d] = o;
    }
}

// ---------------- host orchestration ----------------
extern "C" void kernel_launch(void* const* d_in, const int* in_sizes, int n_in,
                              void* d_out, int out_size)
{
    const float* z_init = (const float*)d_in[0];
    const float* tsteps = (const float*)d_in[1];
    const float* W1     = (const float*)d_in[2];
    const float* b1     = (const float*)d_in[3];
    const float* W2     = (const float*)d_in[4];
    const float* b2     = (const float*)d_in[5];
    const float* W3     = (const float*)d_in[6];
    const float* b3     = (const float*)d_in[7];
    const float* Wqkv   = (const float*)d_in[8];
    const float* bqkv   = (const float*)d_in[9];
    const float* Wo     = (const float*)d_in[10];
    const float* bo     = (const float*)d_in[11];
    const float* gamma  = (const float*)d_in[12];
    const float* beta   = (const float*)d_in[13];

    float *qkv;
    __half *w1p, *w2p, *w3p, *wqkvf, *wof, *zdc, *ctxh;
    cudaGetSymbolAddress((void**)&qkv,    g_qkv);
    cudaGetSymbolAddress((void**)&w1p,    g_W1p);
    cudaGetSymbolAddress((void**)&w2p,    g_W2p);
    cudaGetSymbolAddress((void**)&w3p,    g_W3p);
    cudaGetSymbolAddress((void**)&wqkvf,  g_Wqkvf);
    cudaGetSymbolAddress((void**)&wof,    g_Wof);
    cudaGetSymbolAddress((void**)&zdc,    g_zdc);
    cudaGetSymbolAddress((void**)&ctxh,   g_ctxh);

    cudaFuncSetAttribute(attn_kernel, cudaFuncAttributeMaxDynamicSharedMemorySize,
                         ATTN_SMEM_BYTES);
    cudaFuncSetAttribute(ode_kernel, cudaFuncAttributeMaxDynamicSharedMemorySize,
                         SMEM_ODE);
    cudaFuncSetAttribute(hgemm<3*D_>, cudaFuncAttributeMaxDynamicSharedMemorySize,
                         SMEM_HG);
    cudaFuncSetAttribute(hgemm<D_>, cudaFuncAttributeMaxDynamicSharedMemorySize,
                         SMEM_HG);

    // 0) pack weights
    pack_w<<<(HID_ * D_) / 256, 256>>>(W1, w1p, HID_ / 16, D_);
    pack_w<<<(HID_ * HID_) / 256, 256>>>(W2, w2p, HID_ / 16, HID_);
    pack_w<<<(D_ * HID_) / 256, 256>>>(W3, w3p, D_ / 16, HID_);
    pack_wb<<<(3 * D_ * D_) / 256, 256>>>(Wqkv, wqkvf, 3 * D_, D_);
    pack_wb<<<(D_ * D_) / 256, 256>>>(Wo, wof, D_, D_);

    // 1) fused scale + full RK4 trajectory
    ode_kernel<<<B_ / MB, 512, SMEM_ODE>>>(z_init, tsteps, b1, b2, b3);

    // 2) mean over T + z_dc fp16 prep
    zmean_kernel<<<(B_ * D_) / 256, 256>>>();
    zdc_kernel<<<(BT_ * (D_ / 256)), 256>>>(z_init);

    // 3) QKV projection (fp16 tensor cores)
    hgemm<3*D_><<<BT_ / 128, 256, SMEM_HG>>>(zdc, wqkvf, bqkv, qkv);

    // 4) fused attention per (b,h)
    attn_kernel<<<B_ * NH_, 256, ATTN_SMEM_BYTES>>>();

    // 5) output projection (att_out aliased into qkv scratch)
    hgemm<D_><<<BT_ / 128, 256, SMEM_HG>>>(ctxh, wof, bo, qkv);

    // 6) residual + LayerNorm
    ln_kernel<<<BT_, 128>>>(z_init, gamma, beta, (float*)d_out);
}